// round 6
// baseline (speedup 1.0000x reference)
#include <cuda_runtime.h>
#include <math.h>

#define N_PATHS 2048
#define N_STEPS 512
#define N_FWD   40
#define DT_F    (1.0f/512.0f)
#define SHIFT_F 0.02f
// DT^-0.4 / Gamma(0.6) = 2^3.6 / 1.4891922488128176  (pure math constant)
#define SC_CONST 8.142489698f

// ---------------- device scratch ----------------
__device__ float d_g[N_STEPS];             // Toeplitz kernel taps g[k]
__device__ float d_s2[N_STEPS];            // prefix sum of g^2
__device__ float d_vs[N_FWD];              // vol_scale
__device__ float d_mu0[N_FWD];             // mu_0

// ---------------- f32x2 packed helpers (Blackwell FFMA2) ----------------
__device__ __forceinline__ unsigned long long pack2(float a, float b) {
    unsigned long long r;
    asm("mov.b64 %0, {%1, %2};" : "=l"(r) : "f"(a), "f"(b));
    return r;
}
__device__ __forceinline__ void unpack2(unsigned long long v, float& a, float& b) {
    asm("mov.b64 {%0, %1}, %2;" : "=f"(a), "=f"(b) : "l"(v));
}
__device__ __forceinline__ unsigned long long fma2(unsigned long long a,
                                                   unsigned long long b,
                                                   unsigned long long c) {
    unsigned long long d;
    asm("fma.rn.f32x2 %0, %1, %2, %3;" : "=l"(d) : "l"(a), "l"(b), "l"(c));
    return d;
}

// ---------------- K1: precompute g, s2, per-n constants (all fp32) ----------
__global__ void precompute_kernel(const float* __restrict__ F0,
                                  const float* __restrict__ alphas,
                                  const float* __restrict__ tau,
                                  const float* __restrict__ Lam) {
    const int t    = threadIdx.x;
    const int lane = t & 31;
    const int w    = t >> 5;

    float wgt;
    if (t == 0) {
        wgt = 1.0f / 0.6f;
    } else {
        float tf = (float)t;
        wgt = powf(tf, 0.6f) * expm1f(0.6f * log1pf(1.0f / tf)) * (1.0f / 0.6f);
    }
    const float gv = wgt * SC_CONST;
    d_g[t] = gv;

    // warp-shuffle inclusive scan of gv^2
    float v = gv * gv;
    #pragma unroll
    for (int o = 1; o < 32; o <<= 1) {
        float nv = __shfl_up_sync(0xffffffffu, v, o);
        if (lane >= o) v += nv;
    }
    __shared__ float wsum[16];
    if (lane == 31) wsum[w] = v;
    __syncthreads();
    if (w == 0 && lane < 16) {
        float s = wsum[lane];
        #pragma unroll
        for (int o = 1; o < 16; o <<= 1) {
            float nv = __shfl_up_sync(0xffffu, s, o);
            if (lane >= o) s += nv;
        }
        wsum[lane] = s;
    }
    __syncthreads();
    d_s2[t] = v + ((w > 0) ? wsum[w - 1] : 0.0f);

    __shared__ float som[N_FWD];
    if (t < N_FWD) {
        float vs = alphas[t] * sqrtf(fabsf(F0[t] + SHIFT_F));
        d_vs[t]  = vs;
        som[t]   = tau[t] * vs / (1.0f + tau[t] * F0[t]);
    }
    __syncthreads();
    if (t < N_FWD) {
        float acc = 0.0f;
        #pragma unroll 8
        for (int mcol = 0; mcol < N_FWD; mcol++)
            acc += Lam[t * N_FWD + mcol] * som[mcol];
        d_mu0[t] = -d_vs[t] * acc;
    }
}

// ---------------- fused K2+K3 -------------------------------------------------
#define PPB 2
#define FUSED_TPB 128
#define PH2_THREADS (PPB * N_FWD)          // 80

__global__ void __launch_bounds__(FUSED_TPB)
fused_kernel(const float4* __restrict__ dz,
             const float*  __restrict__ F0,
             const float*  __restrict__ rhos,
             const float*  __restrict__ nus,
             const float*  __restrict__ loadings,
             float* __restrict__ out) {
    __shared__ __align__(16) float4 sdz [PPB * N_STEPS];   // 16 KB
    __shared__ __align__(16) float4 sfbm[PPB * N_STEPS];   // 16 KB
    __shared__ __align__(16) float  sgp [N_STEPS + 8];     // sgp[4+k]=g[k], [0..3]=0
    __shared__ float  ss2[N_STEPS];

    const int tid   = threadIdx.x;
    const int pbase = blockIdx.x * PPB;

    for (int i = tid; i < N_STEPS + 8; i += FUSED_TPB)
        sgp[i] = (i >= 4 && i < N_STEPS + 4) ? d_g[i - 4] : 0.0f;
    for (int i = tid; i < N_STEPS; i += FUSED_TPB)
        ss2[i] = d_s2[i];
    for (int i = tid; i < PPB * N_STEPS; i += FUSED_TPB)
        sdz[i] = dz[(size_t)pbase * N_STEPS + i];
    __syncthreads();

    // ---------------- phase 1: convolution ----------------
    {
        const int t0 = tid * 4;            // this thread owns t0..t0+3

        unsigned long long accA[PPB][4], accB[PPB][4];
        #pragma unroll
        for (int q = 0; q < PPB; q++)
            #pragma unroll
            for (int j = 0; j < 4; j++) { accA[q][j] = 0ull; accB[q][j] = 0ull; }

        // rolling window kept pre-packed: wjp = {g[t0+j-s], g[t0+j-s]}
        float4 wv = *(const float4*)&sgp[t0 + 4];
        unsigned long long w0p = pack2(wv.x, wv.x);
        unsigned long long w1p = pack2(wv.y, wv.y);
        unsigned long long w2p = pack2(wv.z, wv.z);
        unsigned long long w3p = pack2(wv.w, wv.w);

        for (int sb = 0; sb <= t0; sb += 4) {
            float4 gn = *(const float4*)&sgp[t0 - sb];
            #pragma unroll
            for (int i = 0; i < 4; i++) {
                const int s = sb + i;
                #pragma unroll
                for (int q = 0; q < PPB; q++) {
                    float4 zv = sdz[q * N_STEPS + s];
                    unsigned long long zA = pack2(zv.x, zv.y);
                    unsigned long long zB = pack2(zv.z, zv.w);
                    accA[q][0] = fma2(w0p, zA, accA[q][0]);
                    accB[q][0] = fma2(w0p, zB, accB[q][0]);
                    accA[q][1] = fma2(w1p, zA, accA[q][1]);
                    accB[q][1] = fma2(w1p, zB, accB[q][1]);
                    accA[q][2] = fma2(w2p, zA, accA[q][2]);
                    accB[q][2] = fma2(w2p, zB, accB[q][2]);
                    accA[q][3] = fma2(w3p, zA, accA[q][3]);
                    accB[q][3] = fma2(w3p, zB, accB[q][3]);
                }
                float gnew = (i == 0) ? gn.w : (i == 1) ? gn.z : (i == 2) ? gn.y : gn.x;
                w3p = w2p; w2p = w1p; w1p = w0p; w0p = pack2(gnew, gnew);
            }
        }

        #pragma unroll
        for (int q = 0; q < PPB; q++)
            #pragma unroll
            for (int j = 0; j < 4; j++) {
                float a, b, c, d;
                unpack2(accA[q][j], a, b);
                unpack2(accB[q][j], c, d);
                sfbm[q * N_STEPS + t0 + j] = make_float4(a, b, c, d);
            }
    }
    __syncthreads();

    // ---------------- phase 2: mix / exp / dF / cumsum / store ----------------
    if (tid < PH2_THREADS) {
        const int q = tid / N_FWD;
        const int n = tid - q * N_FWD;
        const int p = pbase + q;

        const float rho = rhos[n];
        const float nu  = nus[n];
        const float sq  = sqrtf(fmaxf(1.0f - rho * rho, 0.0f));
        const float l0  = loadings[n * 3 + 0];
        const float l1  = loadings[n * 3 + 1];
        const float l2  = loadings[n * 3 + 2];
        const float vs   = d_vs[n];
        const float muDT = d_mu0[n] * DT_F;
        const float cvar = 0.5f * nu * nu * DT_F;
        const float f0   = F0[n];

        const float4* fb  = sfbm + q * N_STEPS;
        const float4* zp  = sdz  + q * N_STEPS;
        float* op = out + (size_t)p * (N_STEPS + 1) * N_FWD + n;

        float acc = f0;
        __stcs(op, f0);
        op += N_FWD;

        #pragma unroll 1
        for (int t = 0; t < N_STEPS; t += 2) {
            float4 f0v = fb[t];
            float4 z0v = zp[t];
            float4 f1v = fb[t + 1];
            float4 z1v = zp[t + 1];
            float s20 = ss2[t];
            float s21 = ss2[t + 1];

            float crv0 = f0v.x * l0 + f0v.y * l1 + f0v.z * l2;
            float crv1 = f1v.x * l0 + f1v.y * l1 + f1v.z * l2;
            float wr0  = z0v.x * l0 + z0v.y * l1 + z0v.z * l2;
            float wr1  = z1v.x * l0 + z1v.y * l1 + z1v.z * l2;
            float u0   = __expf(nu * (rho * crv0 + sq * f0v.w) - cvar * s20);
            float u1   = __expf(nu * (rho * crv1 + sq * f1v.w) - cvar * s21);

            acc += muDT * (u0 * u0) + wr0 * (u0 * vs);
            __stcs(op, acc);
            op += N_FWD;
            acc += muDT * (u1 * u1) + wr1 * (u1 * vs);
            __stcs(op, acc);
            op += N_FWD;
        }
    }
}

// ---------------- launcher ----------------
extern "C" void kernel_launch(void* const* d_in, const int* in_sizes, int n_in,
                              void* d_out, int out_size) {
    const float* dz       = (const float*)d_in[0];   // (2048, 512, 4)
    const float* F0       = (const float*)d_in[1];   // (40,)
    const float* alphas   = (const float*)d_in[2];   // (40,)
    const float* rhos     = (const float*)d_in[3];   // (40,)
    const float* nus      = (const float*)d_in[4];   // (40,)
    const float* tau      = (const float*)d_in[5];   // (40,)
    const float* loadings = (const float*)d_in[6];   // (40, 3)
    const float* Lam      = (const float*)d_in[7];   // (40, 40)
    float* out = (float*)d_out;                      // (2048, 513, 40)

    // Max shared-memory carveout: static smem is 37KB/block; default carveout
    // caps residency at ~4 blocks/SM. Max carveout (228KB) allows 6 blocks/SM.
    static int carveout_set = 0;
    if (!carveout_set) {
        cudaFuncSetAttribute(fused_kernel,
                             cudaFuncAttributePreferredSharedMemoryCarveout, 100);
        carveout_set = 1;
    }

    precompute_kernel<<<1, N_STEPS>>>(F0, alphas, tau, Lam);
    fused_kernel<<<N_PATHS / PPB, FUSED_TPB>>>(
        (const float4*)dz, F0, rhos, nus, loadings, out);
}

// round 10
// speedup vs baseline: 1.0756x; 1.0756x over previous
#include <cuda_runtime.h>
#include <math.h>

#define N_PATHS 2048
#define N_STEPS 512
#define N_FWD   40
#define DT_F    (1.0f/512.0f)
#define SHIFT_F 0.02f
// DT^-0.4 / Gamma(0.6) = 2^3.6 / 1.4891922488128176  (pure math constant)
#define SC_CONST 8.142489698f

// ---------------- device scratch ----------------
__device__ float d_g[N_STEPS];             // Toeplitz kernel taps g[k]
__device__ float d_s2[N_STEPS];            // prefix sum of g^2
__device__ float d_vs[N_FWD];              // vol_scale
__device__ float d_mu0[N_FWD];             // mu_0

// ---------------- f32x2 packed helpers (Blackwell FFMA2) ----------------
__device__ __forceinline__ unsigned long long pack2(float a, float b) {
    unsigned long long r;
    asm("mov.b64 %0, {%1, %2};" : "=l"(r) : "f"(a), "f"(b));
    return r;
}
__device__ __forceinline__ void unpack2(unsigned long long v, float& a, float& b) {
    asm("mov.b64 {%0, %1}, %2;" : "=f"(a), "=f"(b) : "l"(v));
}
__device__ __forceinline__ unsigned long long fma2(unsigned long long a,
                                                   unsigned long long b,
                                                   unsigned long long c) {
    unsigned long long d;
    asm("fma.rn.f32x2 %0, %1, %2, %3;" : "=l"(d) : "l"(a), "l"(b), "l"(c));
    return d;
}

// ---------------- K1: precompute g, s2, per-n constants (all fp32) ----------
__global__ void precompute_kernel(const float* __restrict__ F0,
                                  const float* __restrict__ alphas,
                                  const float* __restrict__ tau,
                                  const float* __restrict__ Lam) {
    const int t    = threadIdx.x;
    const int lane = t & 31;
    const int w    = t >> 5;

    float wgt;
    if (t == 0) {
        wgt = 1.0f / 0.6f;
    } else {
        float tf = (float)t;
        wgt = powf(tf, 0.6f) * expm1f(0.6f * log1pf(1.0f / tf)) * (1.0f / 0.6f);
    }
    const float gv = wgt * SC_CONST;
    d_g[t] = gv;

    // warp-shuffle inclusive scan of gv^2
    float v = gv * gv;
    #pragma unroll
    for (int o = 1; o < 32; o <<= 1) {
        float nv = __shfl_up_sync(0xffffffffu, v, o);
        if (lane >= o) v += nv;
    }
    __shared__ float wsum[16];
    if (lane == 31) wsum[w] = v;
    __syncthreads();
    if (w == 0 && lane < 16) {
        float s = wsum[lane];
        #pragma unroll
        for (int o = 1; o < 16; o <<= 1) {
            float nv = __shfl_up_sync(0xffffu, s, o);
            if (lane >= o) s += nv;
        }
        wsum[lane] = s;
    }
    __syncthreads();
    d_s2[t] = v + ((w > 0) ? wsum[w - 1] : 0.0f);

    __shared__ float som[N_FWD];
    if (t < N_FWD) {
        float vs = alphas[t] * sqrtf(fabsf(F0[t] + SHIFT_F));
        d_vs[t]  = vs;
        som[t]   = tau[t] * vs / (1.0f + tau[t] * F0[t]);
    }
    __syncthreads();
    if (t < N_FWD) {
        float acc = 0.0f;
        #pragma unroll 8
        for (int mcol = 0; mcol < N_FWD; mcol++)
            acc += Lam[t * N_FWD + mcol] * som[mcol];
        d_mu0[t] = -d_vs[t] * acc;
    }
}

// ---------------- fused K2+K3 (dynamic smem for 6 blocks/SM) ------------------
#define PPB 2
#define FUSED_TPB 128
#define PH2_THREADS (PPB * N_FWD)          // 80

// dynamic smem layout (bytes)
#define OFF_SDZ  0                                        // float4[PPB*512]  16KB
#define OFF_SFBM (OFF_SDZ  + PPB * N_STEPS * 16)          // float4[PPB*512]  16KB
#define OFF_SGP  (OFF_SFBM + PPB * N_STEPS * 16)          // float[520]       2080B
#define OFF_SS2  (OFF_SGP  + (N_STEPS + 8) * 4)           // float[512]       2048B
#define SMEM_BYTES (OFF_SS2 + N_STEPS * 4)                // 36896B

__global__ void __launch_bounds__(FUSED_TPB)
fused_kernel(const float4* __restrict__ dz,
             const float*  __restrict__ F0,
             const float*  __restrict__ rhos,
             const float*  __restrict__ nus,
             const float*  __restrict__ loadings,
             float* __restrict__ out) {
    extern __shared__ __align__(16) char smem_raw[];
    float4* sdz  = (float4*)(smem_raw + OFF_SDZ);
    float4* sfbm = (float4*)(smem_raw + OFF_SFBM);
    float*  sgp  = (float*) (smem_raw + OFF_SGP);   // sgp[4+k]=g[k], [0..3]=0
    float*  ss2  = (float*) (smem_raw + OFF_SS2);

    const int tid   = threadIdx.x;
    const int pbase = blockIdx.x * PPB;

    for (int i = tid; i < N_STEPS + 8; i += FUSED_TPB)
        sgp[i] = (i >= 4 && i < N_STEPS + 4) ? d_g[i - 4] : 0.0f;
    for (int i = tid; i < N_STEPS; i += FUSED_TPB)
        ss2[i] = d_s2[i];
    for (int i = tid; i < PPB * N_STEPS; i += FUSED_TPB)
        sdz[i] = dz[(size_t)pbase * N_STEPS + i];
    __syncthreads();

    // ---------------- phase 1: convolution ----------------
    {
        const int t0 = tid * 4;            // this thread owns t0..t0+3

        unsigned long long accA[PPB][4], accB[PPB][4];
        #pragma unroll
        for (int q = 0; q < PPB; q++)
            #pragma unroll
            for (int j = 0; j < 4; j++) { accA[q][j] = 0ull; accB[q][j] = 0ull; }

        // rolling window w[j] = g[t0 + j - s]
        float4 wv = *(const float4*)&sgp[t0 + 4];
        float w0 = wv.x, w1 = wv.y, w2 = wv.z, w3 = wv.w;

        for (int sb = 0; sb <= t0; sb += 4) {
            float4 gn = *(const float4*)&sgp[t0 - sb];
            #pragma unroll
            for (int i = 0; i < 4; i++) {
                const int s = sb + i;
                unsigned long long gw0 = pack2(w0, w0);
                unsigned long long gw1 = pack2(w1, w1);
                unsigned long long gw2 = pack2(w2, w2);
                unsigned long long gw3 = pack2(w3, w3);
                #pragma unroll
                for (int q = 0; q < PPB; q++) {
                    float4 zv = sdz[q * N_STEPS + s];
                    unsigned long long zA = pack2(zv.x, zv.y);
                    unsigned long long zB = pack2(zv.z, zv.w);
                    accA[q][0] = fma2(gw0, zA, accA[q][0]);
                    accB[q][0] = fma2(gw0, zB, accB[q][0]);
                    accA[q][1] = fma2(gw1, zA, accA[q][1]);
                    accB[q][1] = fma2(gw1, zB, accB[q][1]);
                    accA[q][2] = fma2(gw2, zA, accA[q][2]);
                    accB[q][2] = fma2(gw2, zB, accB[q][2]);
                    accA[q][3] = fma2(gw3, zA, accA[q][3]);
                    accB[q][3] = fma2(gw3, zB, accB[q][3]);
                }
                float gnew = (i == 0) ? gn.w : (i == 1) ? gn.z : (i == 2) ? gn.y : gn.x;
                w3 = w2; w2 = w1; w1 = w0; w0 = gnew;
            }
        }

        #pragma unroll
        for (int q = 0; q < PPB; q++)
            #pragma unroll
            for (int j = 0; j < 4; j++) {
                float a, b, c, d;
                unpack2(accA[q][j], a, b);
                unpack2(accB[q][j], c, d);
                sfbm[q * N_STEPS + t0 + j] = make_float4(a, b, c, d);
            }
    }
    __syncthreads();

    // ---------------- phase 2: mix / exp / dF / cumsum / store ----------------
    if (tid < PH2_THREADS) {
        const int q = tid / N_FWD;
        const int n = tid - q * N_FWD;
        const int p = pbase + q;

        const float rho = rhos[n];
        const float nu  = nus[n];
        const float sq  = sqrtf(fmaxf(1.0f - rho * rho, 0.0f));
        const float l0  = loadings[n * 3 + 0];
        const float l1  = loadings[n * 3 + 1];
        const float l2  = loadings[n * 3 + 2];
        const float vs   = d_vs[n];
        const float muDT = d_mu0[n] * DT_F;
        const float cvar = 0.5f * nu * nu * DT_F;
        const float f0   = F0[n];

        const float4* fb  = sfbm + q * N_STEPS;
        const float4* zp  = sdz  + q * N_STEPS;
        float* op = out + (size_t)p * (N_STEPS + 1) * N_FWD + n;

        float acc = f0;
        __stcs(op, f0);
        op += N_FWD;

        for (int t = 0; t < N_STEPS; t++) {
            float4 f = fb[t];
            float4 z = zp[t];
            float fbm_curve = f.x * l0 + f.y * l1 + f.z * l2;
            float fbm = rho * fbm_curve + sq * f.w;
            float wr  = z.x * l0 + z.y * l1 + z.z * l2;
            float u   = __expf(nu * fbm - cvar * ss2[t]);
            acc += muDT * (u * u) + wr * (u * vs);
            __stcs(op, acc);
            op += N_FWD;
        }
    }
}

// ---------------- launcher ----------------
extern "C" void kernel_launch(void* const* d_in, const int* in_sizes, int n_in,
                              void* d_out, int out_size) {
    const float* dz       = (const float*)d_in[0];   // (2048, 512, 4)
    const float* F0       = (const float*)d_in[1];   // (40,)
    const float* alphas   = (const float*)d_in[2];   // (40,)
    const float* rhos     = (const float*)d_in[3];   // (40,)
    const float* nus      = (const float*)d_in[4];   // (40,)
    const float* tau      = (const float*)d_in[5];   // (40,)
    const float* loadings = (const float*)d_in[6];   // (40, 3)
    const float* Lam      = (const float*)d_in[7];   // (40, 40)
    float* out = (float*)d_out;                      // (2048, 513, 40)

    // Dynamic smem (36.9KB/block) + opt-in max: 6 blocks/SM (221KB <= 228KB),
    // vs 4 blocks at the default carveout with static smem.
    cudaFuncSetAttribute(fused_kernel,
                         cudaFuncAttributeMaxDynamicSharedMemorySize, SMEM_BYTES);

    precompute_kernel<<<1, N_STEPS>>>(F0, alphas, tau, Lam);
    fused_kernel<<<N_PATHS / PPB, FUSED_TPB, SMEM_BYTES>>>(
        (const float4*)dz, F0, rhos, nus, loadings, out);
}